// round 17
// baseline (speedup 1.0000x reference)
#include <cuda_runtime.h>
#include <cuda_fp16.h>
#include <cstdint>

#define KP 6
#define BB 256
#define DD 256
#define NN 50000
#define TOPK 5
#define NTILES 391                         // ceil(NN/128)
#define NCAND 16                           // approx candidates for exact rescore

// ---------------------------------------------------------------------------
// static device scratch
// ---------------------------------------------------------------------------
__device__ float g_invF[KP * BB];
__device__ float g_invM[KP * NN];
__device__ __half g_Asplit[(size_t)KP * BB * 512];   // [k][m][hi(256)|lo(256)] fp16
__device__ __half g_Bh[(size_t)KP * NN * 256];       // [k][n][256] fp16
__device__ float g_simScratch[(size_t)KP * BB * NN]; // fallback only
__device__ float g_bmax[(size_t)KP * BB * NTILES];   // per-row per-tile max

// ---------------------------------------------------------------------------
// helpers
// ---------------------------------------------------------------------------
__device__ __forceinline__ uint32_t smem_u32(const void* p) {
    uint32_t a;
    asm("{ .reg .u64 t; cvta.to.shared.u64 t, %1; cvt.u32.u64 %0, t; }"
        : "=r"(a) : "l"(p));
    return a;
}

#define CP16(dst, src) \
    asm volatile("cp.async.cg.shared.global [%0], [%1], 16;" \
                 :: "r"(dst), "l"(src) : "memory")
#define CP_COMMIT() asm volatile("cp.async.commit_group;" ::: "memory")
#define CP_WAIT1()  asm volatile("cp.async.wait_group 1;" ::: "memory")

#define LDSM4(r, addr)                                                          \
    asm volatile("ldmatrix.sync.aligned.m8n8.x4.shared.b16 {%0,%1,%2,%3}, [%4];"\
                 : "=r"((r)[0]), "=r"((r)[1]), "=r"((r)[2]), "=r"((r)[3])       \
                 : "r"(addr))

#define MMA_F16(d, a, b)                                                        \
    asm volatile("mma.sync.aligned.m16n8k16.row.col.f32.f16.f16.f32 "           \
                 "{%0,%1,%2,%3}, {%4,%5,%6,%7}, {%8,%9}, {%0,%1,%2,%3};"        \
                 : "+f"((d)[0]), "+f"((d)[1]), "+f"((d)[2]), "+f"((d)[3])       \
                 : "r"((a)[0]), "r"((a)[1]), "r"((a)[2]), "r"((a)[3]),          \
                   "r"((b)[0]), "r"((b)[1]))

// ---------------------------------------------------------------------------
// Combined norm + fp16 conversion for BOTH tensors. 4 rows per warp (MLP=8).
// feat rows -> hi/lo split layout [512]; mem rows -> plain fp16 [256].
// Numeric operations identical to the round-12 kernels.
// ---------------------------------------------------------------------------
__device__ __forceinline__ void split_writeA(__half* drow, int col, float4 v) {
    float xs[4] = {v.x, v.y, v.z, v.w};
    uint32_t hp[2], lp[2];
#pragma unroll
    for (int q = 0; q < 2; ++q) {
        __half h0 = __float2half_rn(xs[2 * q + 0]);
        __half h1 = __float2half_rn(xs[2 * q + 1]);
        __half l0 = __float2half_rn(xs[2 * q + 0] - __half2float(h0));
        __half l1 = __float2half_rn(xs[2 * q + 1] - __half2float(h1));
        hp[q] = (uint32_t)__half_as_ushort(h0) | ((uint32_t)__half_as_ushort(h1) << 16);
        lp[q] = (uint32_t)__half_as_ushort(l0) | ((uint32_t)__half_as_ushort(l1) << 16);
    }
    *(uint2*)(drow + col)       = make_uint2(hp[0], hp[1]);
    *(uint2*)(drow + 256 + col) = make_uint2(lp[0], lp[1]);
}

__device__ __forceinline__ void write_h4(__half* drow, int col, float4 v) {
    __half h0 = __float2half_rn(v.x), h1 = __float2half_rn(v.y);
    __half h2 = __float2half_rn(v.z), h3 = __float2half_rn(v.w);
    uint32_t p0 = (uint32_t)__half_as_ushort(h0) | ((uint32_t)__half_as_ushort(h1) << 16);
    uint32_t p1 = (uint32_t)__half_as_ushort(h2) | ((uint32_t)__half_as_ushort(h3) << 16);
    *(uint2*)(drow + col) = make_uint2(p0, p1);
}

__device__ __forceinline__ float warp_sumsq(float4 a, float4 b) {
    float s = a.x * a.x + a.y * a.y + a.z * a.z + a.w * a.w
            + b.x * b.x + b.y * b.y + b.z * b.z + b.w * b.w;
#pragma unroll
    for (int o = 16; o; o >>= 1) s += __shfl_xor_sync(0xFFFFFFFFu, s, o);
    return s;
}

#define ROWS_F (KP * BB)                 // 1536
#define WARPS_F (ROWS_F / 4)             // 384
#define ROWS_M (KP * NN)                 // 300000
#define WARPS_M ((ROWS_M + 3) / 4)       // 75000
#define CONV_WARPS (WARPS_F + WARPS_M)

__global__ void norm_conv_all(const float* __restrict__ feat,
                              const float* __restrict__ mem,
                              __half* __restrict__ Asp,
                              __half* __restrict__ Bh,
                              float* __restrict__ invF,
                              float* __restrict__ invM) {
    int gw = (blockIdx.x * blockDim.x + threadIdx.x) >> 5;
    int lane = threadIdx.x & 31;
    if (gw >= CONV_WARPS) return;

    if (gw < WARPS_F) {
        int base = gw * 4;
        float4 v0[4], v1[4];
#pragma unroll
        for (int r = 0; r < 4; ++r) {
            const float4* p = (const float4*)(feat + (size_t)(base + r) * DD);
            v0[r] = p[lane];
            v1[r] = p[lane + 32];
        }
#pragma unroll
        for (int r = 0; r < 4; ++r) {
            float s = warp_sumsq(v0[r], v1[r]);
            if (lane == 0) invF[base + r] = 1.0f / fmaxf(sqrtf(s), 1e-12f);
            __half* drow = Asp + (size_t)(base + r) * 512;
            split_writeA(drow, lane * 4, v0[r]);
            split_writeA(drow, lane * 4 + 128, v1[r]);
        }
    } else {
        int base = (gw - WARPS_F) * 4;
        int nr = min(4, ROWS_M - base);
        float4 v0[4], v1[4];
        for (int r = 0; r < nr; ++r) {
            const float4* p = (const float4*)(mem + (size_t)(base + r) * DD);
            v0[r] = p[lane];
            v1[r] = p[lane + 32];
        }
        for (int r = 0; r < nr; ++r) {
            float s = warp_sumsq(v0[r], v1[r]);
            if (lane == 0) invM[base + r] = 1.0f / fmaxf(sqrtf(s), 1e-12f);
            __half* drow = Bh + (size_t)(base + r) * 256;
            write_h4(drow, lane * 4, v0[r]);
            write_h4(drow, lane * 4 + 128, v1[r]);
        }
    }
}

// ---------------------------------------------------------------------------
// fp16 HMMA GEMM, 2-term A split sharing one B tile per chunk (round-12).
// 8 kc chunks of 32. 3-stage ring, depth-2 prefetch.
// + fused soft zero-fill + per-(row,tile) max into g_bmax.
// ---------------------------------------------------------------------------
#define BM 128
#define BN 128
#define NCHUNK 8
#define STAGES 3
#define TILE_BYTES (128 * 40 * 2)          // 10240 (80B rows)
#define STAGE_BYTES (3 * TILE_BYTES)       // Ahi + Alo + B
#define GEMM_SMEM (STAGES * STAGE_BYTES + 1024)

__global__ void __launch_bounds__(256)
gemm_hmma_kernel(const __half* __restrict__ Asp,
                 const __half* __restrict__ Bh,
                 float* __restrict__ C,
                 float* __restrict__ soft,
                 const float* __restrict__ invF,
                 const float* __restrict__ invM,
                 float* __restrict__ bmax) {
    extern __shared__ char smem[];
    const int k  = blockIdx.z;
    const int m0 = blockIdx.y * BM;
    const int n0 = blockIdx.x * BN;
    const int tid = threadIdx.x;
    const int wid = tid >> 5, lid = tid & 31;

    float* invFsm = (float*)(smem + STAGES * STAGE_BYTES);
    float* invMsm = invFsm + 128;
    if (tid < 128) {
        invFsm[tid] = invF[k * BB + m0 + tid];
    } else {
        int t = tid - 128;
        int n = n0 + t;
        invMsm[t] = (n < NN) ? invM[k * NN + n] : 0.0f;
    }

    const __half* Ak = Asp + (size_t)k * BB * 512;
    const __half* Bk = Bh + (size_t)k * NN * 256;
    const uint32_t sbase = smem_u32(smem);

    auto issue_chunk = [&](int c) {
        const uint32_t s = sbase + (c % STAGES) * STAGE_BYTES;
        const int ko = c * 32;
#pragma unroll
        for (int it = 0; it < 2; ++it) {
            int i = tid + it * 256;
            int row = i >> 2, seg = i & 3;
            uint32_t so = row * 80 + seg * 16;
            const __half* arow = Ak + (size_t)(m0 + row) * 512 + ko + seg * 8;
            CP16(s + so, arow);                            // A hi
            CP16(s + TILE_BYTES + so, arow + 256);         // A lo
            int gr = min(n0 + row, NN - 1);
            CP16(s + 2 * TILE_BYTES + so,
                 Bk + (size_t)gr * 256 + ko + seg * 8);    // B
        }
        CP_COMMIT();
    };

    float acc[4][4][4];
#pragma unroll
    for (int mt = 0; mt < 4; ++mt)
#pragma unroll
        for (int nt = 0; nt < 4; ++nt)
#pragma unroll
            for (int r = 0; r < 4; ++r) acc[mt][nt][r] = 0.0f;

    issue_chunk(0);
    issue_chunk(1);

    const int warp_m = wid >> 2;
    const int warp_n = wid & 3;

    for (int c = 0; c < NCHUNK; ++c) {
        CP_WAIT1();
        __syncthreads();
        if (c + 2 < NCHUNK) issue_chunk(c + 2);

        const uint32_t sAh = sbase + (c % STAGES) * STAGE_BYTES;
        const uint32_t sAl = sAh + TILE_BYTES;
        const uint32_t sB  = sAh + 2 * TILE_BYTES;
#pragma unroll
        for (int ks = 0; ks < 2; ++ks) {
            uint32_t b[4][2];
#pragma unroll
            for (int np = 0; np < 2; ++np) {
                uint32_t bb[4];
                int grp = lid >> 3, r = lid & 7;
                int row = warp_n * 32 + np * 16 + (grp >> 1) * 8 + r;
                int col = ks * 16 + (grp & 1) * 8;
                LDSM4(bb, sB + row * 80 + col * 2);
                b[np * 2 + 0][0] = bb[0]; b[np * 2 + 0][1] = bb[1];
                b[np * 2 + 1][0] = bb[2]; b[np * 2 + 1][1] = bb[3];
            }
            uint32_t a[4][4];
#pragma unroll
            for (int mt = 0; mt < 4; ++mt) {
                int row = warp_m * 64 + mt * 16 + (lid & 15);
                int col = ks * 16 + (lid >> 4) * 8;
                LDSM4(a[mt], sAh + row * 80 + col * 2);
            }
#pragma unroll
            for (int mt = 0; mt < 4; ++mt)
#pragma unroll
                for (int nt = 0; nt < 4; ++nt)
                    MMA_F16(acc[mt][nt], a[mt], b[nt]);
#pragma unroll
            for (int mt = 0; mt < 4; ++mt) {
                int row = warp_m * 64 + mt * 16 + (lid & 15);
                int col = ks * 16 + (lid >> 4) * 8;
                LDSM4(a[mt], sAl + row * 80 + col * 2);
            }
#pragma unroll
            for (int mt = 0; mt < 4; ++mt)
#pragma unroll
                for (int nt = 0; nt < 4; ++nt)
                    MMA_F16(acc[mt][nt], a[mt], b[nt]);
        }
    }
    __syncthreads();

    // epilogue: write sim, zero soft, accumulate per-row tile max
    float (*rowmax)[4] = (float(*)[4])smem;
    const int g = lid >> 2, tig = lid & 3;
    const float2 z2 = make_float2(0.f, 0.f);
#pragma unroll
    for (int mt = 0; mt < 4; ++mt) {
        int mA = warp_m * 64 + mt * 16;
        float fi0 = invFsm[mA + g];
        float fi1 = invFsm[mA + g + 8];
        size_t row0 = (size_t)k * BB + m0 + mA + g;
        float* r0 = C + row0 * NN;
        float* r1 = r0 + 8 * NN;
        float* z0 = soft + row0 * NN;
        float* z1 = z0 + 8 * NN;
        float rm0 = -3.0e38f, rm1 = -3.0e38f;
#pragma unroll
        for (int nt = 0; nt < 4; ++nt) {
            int nA = warp_n * 32 + nt * 8 + tig * 2;
            int n = n0 + nA;
            float im0 = invMsm[nA], im1 = invMsm[nA + 1];
            float v00 = acc[mt][nt][0] * fi0 * im0;
            float v01 = acc[mt][nt][1] * fi0 * im1;
            float v10 = acc[mt][nt][2] * fi1 * im0;
            float v11 = acc[mt][nt][3] * fi1 * im1;
            if (n + 1 < NN) {
                *(float2*)(r0 + n) = make_float2(v00, v01);
                *(float2*)(r1 + n) = make_float2(v10, v11);
                *(float2*)(z0 + n) = z2;
                *(float2*)(z1 + n) = z2;
                rm0 = fmaxf(rm0, fmaxf(v00, v01));
                rm1 = fmaxf(rm1, fmaxf(v10, v11));
            } else if (n < NN) {
                r0[n] = v00; r1[n] = v10;
                z0[n] = 0.f; z1[n] = 0.f;
                rm0 = fmaxf(rm0, v00);
                rm1 = fmaxf(rm1, v10);
            }
        }
        rm0 = fmaxf(rm0, __shfl_xor_sync(0xFFFFFFFFu, rm0, 1));
        rm0 = fmaxf(rm0, __shfl_xor_sync(0xFFFFFFFFu, rm0, 2));
        rm1 = fmaxf(rm1, __shfl_xor_sync(0xFFFFFFFFu, rm1, 1));
        rm1 = fmaxf(rm1, __shfl_xor_sync(0xFFFFFFFFu, rm1, 2));
        if (tig == 0) {
            rowmax[mA + g][warp_n] = rm0;
            rowmax[mA + g + 8][warp_n] = rm1;
        }
    }
    __syncthreads();
    if (tid < 128) {
        float v = fmaxf(fmaxf(rowmax[tid][0], rowmax[tid][1]),
                        fmaxf(rowmax[tid][2], rowmax[tid][3]));
        bmax[((size_t)k * BB + m0 + tid) * NTILES + blockIdx.x] = v;
    }
}

// ---------------------------------------------------------------------------
// topk2: (A) warp-0 top-5 of 391 tile maxima -> thr, (B) candidate tiles,
// (C) approx top-16, (D) EXACT fp32 rescore -> top-5, softmax, scatter.
// ---------------------------------------------------------------------------
__global__ void __launch_bounds__(256)
topk2_kernel(const float* __restrict__ bmax,
             const float* __restrict__ sim, float* __restrict__ soft,
             const float* __restrict__ feat, const float* __restrict__ mem,
             const float* __restrict__ invF, const float* __restrict__ invM) {
    const int row = blockIdx.x;
    const int tid = threadIdx.x;
    const int wid = tid >> 5, lid = tid & 31;
    const float* bm = bmax + (size_t)row * NTILES;
    const float* s  = sim + (size_t)row * NN;

    __shared__ float sv[256 * TOPK];
    __shared__ int   si[256 * TOPK];
    __shared__ float thr_sm;
    __shared__ int   candI[NCAND];
    __shared__ float exV[NCAND];
    __shared__ int   exI[NCAND];
    __shared__ int   list[NTILES];
    __shared__ int   cnt;

    float tv[TOPK];
    int   ti[TOPK];

    auto insert = [&](float v, int idx) {
        if (v > tv[TOPK - 1]) {
            tv[TOPK - 1] = v; ti[TOPK - 1] = idx;
#pragma unroll
            for (int p = TOPK - 1; p > 0; --p) {
                if (tv[p] > tv[p - 1]) {
                    float t = tv[p]; tv[p] = tv[p - 1]; tv[p - 1] = t;
                    int   q = ti[p]; ti[p] = ti[p - 1]; ti[p - 1] = q;
                }
            }
        }
    };

    if (tid == 0) cnt = 0;

    // --- phase A: warp 0 finds the 5th-largest tile max (no block barriers)
    if (wid == 0) {
#pragma unroll
        for (int q = 0; q < TOPK; ++q) { tv[q] = -3.0e38f; ti[q] = -1; }
        for (int i = lid; i < NTILES; i += 32) insert(bm[i], i);
        float last = -3.0e38f;
#pragma unroll
        for (int r = 0; r < TOPK; ++r) {
            float m = tv[0];
            float mm = m;
#pragma unroll
            for (int o = 16; o; o >>= 1)
                mm = fmaxf(mm, __shfl_xor_sync(0xFFFFFFFFu, mm, o));
            // pop one instance of mm
            unsigned ballot = __ballot_sync(0xFFFFFFFFu, m == mm);
            int winner = __ffs(ballot) - 1;
            if (lid == winner) {
#pragma unroll
                for (int p = 0; p < TOPK - 1; ++p) tv[p] = tv[p + 1];
                tv[TOPK - 1] = -3.0e38f;
            }
            last = mm;
        }
        if (lid == 0) thr_sm = last - 1e-4f;  // slack (round-12 proven)
    }
    __syncthreads();
    const float thr = thr_sm;

    // --- phase B: collect candidate tiles ---
    for (int i = tid; i < NTILES; i += 256)
        if (bm[i] >= thr) list[atomicAdd(&cnt, 1)] = i;
    __syncthreads();
    const int nl = cnt;

    // --- phase C: per-thread top-5 over candidate elements ---
#pragma unroll
    for (int q = 0; q < TOPK; ++q) { tv[q] = -3.0e38f; ti[q] = -1; }
    const int total = nl * 128;
    for (int e = tid; e < total; e += 256) {
        int tile = list[e >> 7];
        int n = (tile << 7) + (e & 127);
        if (n < NN) insert(s[n], n);
    }
#pragma unroll
    for (int q = 0; q < TOPK; ++q) {
        sv[tid * TOPK + q] = tv[q];
        si[tid * TOPK + q] = ti[q];
    }
    __syncthreads();

    // warp 0: iterative argmax x NCAND over the pooled entries
    if (wid == 0) {
        for (int pass = 0; pass < NCAND; ++pass) {
            float m = -3.0e38f; int ms = -1;
            for (int j = lid; j < 256 * TOPK; j += 32)
                if (sv[j] > m) { m = sv[j]; ms = j; }
#pragma unroll
            for (int o = 16; o; o >>= 1) {
                float om = __shfl_xor_sync(0xFFFFFFFFu, m, o);
                int   oc = __shfl_xor_sync(0xFFFFFFFFu, ms, o);
                if (om > m || (om == m && oc >= 0 && oc < ms)) { m = om; ms = oc; }
            }
            if (lid == 0) {
                candI[pass] = (ms >= 0) ? si[ms] : -1;
                if (ms >= 0) sv[ms] = -3.0e38f;
            }
            __syncwarp();
        }
    }
    __syncthreads();

    // --- phase D: exact fp32 rescore of the NCAND candidates ---
    for (int c = wid; c < NCAND; c += 8) {
        int n = candI[c];
        if (n >= 0) {
            int k = row >> 8;             // row = k*BB + b, BB=256
            const float4* fr = (const float4*)(feat + (size_t)row * DD);
            const float4* mr = (const float4*)(mem + ((size_t)(k * NN + n)) * DD);
            float ssum = 0.0f;
#pragma unroll
            for (int j = 0; j < 2; ++j) {
                float4 a = fr[lid + j * 32];
                float4 b = mr[lid + j * 32];
                ssum += a.x * b.x + a.y * b.y + a.z * b.z + a.w * b.w;
            }
#pragma unroll
            for (int o = 16; o; o >>= 1)
                ssum += __shfl_xor_sync(0xFFFFFFFFu, ssum, o);
            if (lid == 0) {
                exV[c] = ssum * invF[row] * invM[k * NN + n];
                exI[c] = n;
            }
        } else if (lid == 0) {
            exV[c] = -3.0e38f;
            exI[c] = -1;
        }
    }
    __syncthreads();

    // --- exact top-5 among NCAND, softmax, scatter ---
    if (tid == 0) {
#pragma unroll
        for (int q = 0; q < TOPK; ++q) { tv[q] = -3.0e38f; ti[q] = -1; }
#pragma unroll
        for (int c = 0; c < NCAND; ++c) insert(exV[c], exI[c]);
        float mx = tv[0];
        float w[TOPK], sum = 0.0f;
#pragma unroll
        for (int q = 0; q < TOPK; ++q) {
            w[q] = __expf((tv[q] - mx) * (1.0f / 3.0f));
            sum += w[q];
        }
        float invSum = 1.0f / sum;
        float* srow = soft + (size_t)row * NN;
#pragma unroll
        for (int q = 0; q < TOPK; ++q)
            srow[ti[q]] = w[q] * invSum;
    }
}

// ---------------------------------------------------------------------------
extern "C" void kernel_launch(void* const* d_in, const int* in_sizes, int n_in,
                              void* d_out, int out_size) {
    const float* feat = (const float*)d_in[0];  // [KP,BB,DD]
    const float* mem  = (const float*)d_in[1];  // [KP,NN,DD]
    float* out = (float*)d_out;

    const size_t total = (size_t)KP * BB * NN;

    float *invF, *invM, *bmax;
    __half *Asp, *Bh;
    cudaGetSymbolAddress((void**)&invF, g_invF);
    cudaGetSymbolAddress((void**)&invM, g_invM);
    cudaGetSymbolAddress((void**)&Asp, g_Asplit);
    cudaGetSymbolAddress((void**)&Bh, g_Bh);
    cudaGetSymbolAddress((void**)&bmax, g_bmax);

    float* soft = out;
    float* sim;
    if ((size_t)out_size >= 2 * total) {
        sim = out + total;
    } else {
        cudaGetSymbolAddress((void**)&sim, g_simScratch);
    }

    // combined norm + fp16 conversion (A split, B plain), 4 rows/warp
    {
        int blocks = (CONV_WARPS * 32 + 255) / 256;
        norm_conv_all<<<blocks, 256>>>(feat, mem, Asp, Bh, invF, invM);
    }

    // 2-term fp16 HMMA GEMM (+ zero-fill soft, + per-tile row maxima)
    {
        cudaFuncSetAttribute(gemm_hmma_kernel,
                             cudaFuncAttributeMaxDynamicSharedMemorySize, GEMM_SMEM);
        dim3 grid((NN + BN - 1) / BN, BB / BM, KP);  // (391, 2, 6)
        gemm_hmma_kernel<<<grid, 256, GEMM_SMEM>>>(Asp, Bh, sim, soft,
                                                   invF, invM, bmax);
    }

    // hierarchical top-5 with exact rescore + softmax scatter
    topk2_kernel<<<KP * BB, 256>>>(bmax, sim, soft, feat, mem, invF, invM);
}